// round 2
// baseline (speedup 1.0000x reference)
#include <cuda_runtime.h>
#include <cstdint>

typedef unsigned long long ull;

#define BATCH 8192
#define SEQT  256
#define HID   32
#define WPC   4     // warps per CTA
#define CTAS  (BATCH / WPC)

// ---- f32x2 helpers (Blackwell packed fp32) ----
__device__ __forceinline__ void fma2(ull &acc, ull a, ull b) {
    asm("fma.rn.f32x2 %0, %1, %2, %0;" : "+l"(acc) : "l"(a), "l"(b));
}
__device__ __forceinline__ ull pack2(float a, float b) {
    ull r;
    asm("mov.b64 %0, {%1, %2};" : "=l"(r)
        : "r"(__float_as_uint(a)), "r"(__float_as_uint(b)));
    return r;
}
__device__ __forceinline__ float hsum2(ull v) {
    unsigned lo, hi;
    asm("mov.b64 {%0, %1}, %2;" : "=r"(lo), "=r"(hi) : "l"(v));
    return __uint_as_float(lo) + __uint_as_float(hi);
}

// ---- fast activations (EX2/RCP based, ~2 ulp; saturate correctly at +-inf) ----
__device__ __forceinline__ float sigm(float x) {
    return __fdividef(1.0f, 1.0f + __expf(-x));
}
__device__ __forceinline__ float tanhx(float x) {
    return 1.0f - __fdividef(2.0f, __expf(2.0f * x) + 1.0f);
}

__global__ void lstm_ae_kernel(
    const float* __restrict__ x,      // [B, T, 1]
    const float* __restrict__ eWih,   // [128, 1]
    const float* __restrict__ eWhh,   // [128, 32]
    const float* __restrict__ eBih,   // [128]
    const float* __restrict__ eBhh,   // [128]
    const float* __restrict__ dWih,   // [4, 32]
    const float* __restrict__ dWhh,   // [4, 1]
    const float* __restrict__ dBih,   // [4]
    const float* __restrict__ dBhh,   // [4]
    float* __restrict__ out)          // [B, T, 1]
{
    __shared__ float xs[WPC][SEQT];
    __shared__ ull   hb[2][WPC][HID / 2];   // ping-pong h buffers, packed pairs

    const int lane = threadIdx.x & 31;     // hidden index j
    const int w    = threadIdx.x >> 5;
    const int b    = blockIdx.x * WPC + w;

    // ---- stage x row into smem (coalesced) ----
    const float* xrow = x + (size_t)b * SEQT;
    #pragma unroll
    for (int r = 0; r < SEQT / 32; ++r)
        xs[w][r * 32 + lane] = xrow[r * 32 + lane];

    // ---- per-lane recurrent weights, packed over k-pairs ----
    // gate rows: i = lane, f = 32+lane, g = 64+lane, o = 96+lane
    ull wi[16], wf[16], wg[16], wo[16];
    {
        const ull* ri = (const ull*)(eWhh + (size_t)(       lane) * HID);
        const ull* rf = (const ull*)(eWhh + (size_t)(32  + lane) * HID);
        const ull* rg = (const ull*)(eWhh + (size_t)(64  + lane) * HID);
        const ull* ro = (const ull*)(eWhh + (size_t)(96  + lane) * HID);
        #pragma unroll
        for (int k = 0; k < 16; ++k) {
            wi[k] = ri[k]; wf[k] = rf[k]; wg[k] = rg[k]; wo[k] = ro[k];
        }
    }
    const float bi = eBih[lane]      + eBhh[lane];
    const float bf = eBih[32 + lane] + eBhh[32 + lane];
    const float bg = eBih[64 + lane] + eBhh[64 + lane];
    const float bo = eBih[96 + lane] + eBhh[96 + lane];
    const float vi = eWih[lane];
    const float vf = eWih[32 + lane];
    const float vg = eWih[64 + lane];
    const float vo = eWih[96 + lane];

    // init h buffer 0 to zeros
    ((float*)hb[0][w])[lane] = 0.0f;
    __syncwarp();

    float h = 0.0f, c = 0.0f;

    // ---- encoder: 256 steps, ping-pong parity via unroll-by-2 ----
    #pragma unroll 1
    for (int t = 0; t < SEQT; t += 2) {
        #pragma unroll
        for (int p = 0; p < 2; ++p) {
            const ull* rb = hb[p][w];
            float*     wb = (float*)hb[p ^ 1][w];
            const float xv = xs[w][t + p];

            ull ai = pack2(fmaf(xv, vi, bi), 0.0f);
            ull af = pack2(fmaf(xv, vf, bf), 0.0f);
            ull ag = pack2(fmaf(xv, vg, bg), 0.0f);
            ull ao = pack2(fmaf(xv, vo, bo), 0.0f);

            #pragma unroll
            for (int k = 0; k < 16; ++k) {
                const ull h2 = rb[k];            // LDS.64 broadcast
                fma2(ai, wi[k], h2);
                fma2(af, wf[k], h2);
                fma2(ag, wg[k], h2);
                fma2(ao, wo[k], h2);
            }

            const float I = sigm(hsum2(ai));
            const float F = sigm(hsum2(af));
            const float G = tanhx(hsum2(ag));
            const float O = sigm(hsum2(ao));
            c = fmaf(F, c, I * G);
            h = O * tanhx(c);

            wb[lane] = h;
            __syncwarp();
        }
    }

    // ---- decoder input projection: u_g = sum_j dWih[g][j] * h[j] ----
    float p0 = h * dWih[lane];
    float p1 = h * dWih[32 + lane];
    float p2 = h * dWih[64 + lane];
    float p3 = h * dWih[96 + lane];
    #pragma unroll
    for (int m = 16; m > 0; m >>= 1) {
        p0 += __shfl_xor_sync(0xffffffffu, p0, m);
        p1 += __shfl_xor_sync(0xffffffffu, p1, m);
        p2 += __shfl_xor_sync(0xffffffffu, p2, m);
        p3 += __shfl_xor_sync(0xffffffffu, p3, m);
    }
    const float pre0 = p0 + dBih[0] + dBhh[0];
    const float pre1 = p1 + dBih[1] + dBhh[1];
    const float pre2 = p2 + dBih[2] + dBhh[2];
    const float pre3 = p3 + dBih[3] + dBhh[3];
    const float q0 = dWhh[0], q1 = dWhh[1], q2 = dWhh[2], q3 = dWhh[3];

    // ---- decoder: H=1 scalar recurrence, run redundantly on all lanes;
    //      lane s keeps step (chunk*32 + s) -> coalesced 128B stores ----
    float hd = 0.0f, cd = 0.0f;
    float* orow = out + (size_t)b * SEQT;
    #pragma unroll 1
    for (int ch = 0; ch < 8; ++ch) {
        float keep = 0.0f;
        #pragma unroll 1
        for (int s = 0; s < 32; ++s) {
            const float I = sigm(fmaf(hd, q0, pre0));
            const float F = sigm(fmaf(hd, q1, pre1));
            const float G = tanhx(fmaf(hd, q2, pre2));
            const float O = sigm(fmaf(hd, q3, pre3));
            cd = fmaf(F, cd, I * G);
            hd = O * tanhx(cd);
            keep = (lane == s) ? hd : keep;
        }
        orow[ch * 32 + lane] = keep;
    }
}

extern "C" void kernel_launch(void* const* d_in, const int* in_sizes, int n_in,
                              void* d_out, int out_size) {
    (void)in_sizes; (void)n_in; (void)out_size;
    lstm_ae_kernel<<<CTAS, WPC * 32>>>(
        (const float*)d_in[0],
        (const float*)d_in[1], (const float*)d_in[2],
        (const float*)d_in[3], (const float*)d_in[4],
        (const float*)d_in[5], (const float*)d_in[6],
        (const float*)d_in[7], (const float*)d_in[8],
        (float*)d_out);
}